// round 14
// baseline (speedup 1.0000x reference)
#include <cuda_runtime.h>

#define NV 32
#define NT 8192
#define NT1 8191
#define NL 16
#define NC 512
#define NKF 256    /* filter chunks of 32 steps */
#define CHF 32
#define NSF 16     /* supers of 16 chunks (512 steps) */
#define NQS 512    /* solve sub-chunks of 16 steps */
#define CHS 16

#define OFF_P  8388608u
#define OFF_MZ 25165824u
#define OFF_PZ 29360128u
#define OFF_LP 33554432u

#define F_JITTER 1e-6f
#define F_LOG2PI 1.8378770664093453f
#define SQRT3    1.7320508075688772f

#define SOLVE_SMEM (128*17*8 + 128*17*16)

__device__ float  g_lpp[NKF * NC];
// filter chunk composites (A, b, C, eta, J)
__device__ float4 g_feA[NKF * NC];
__device__ float4 g_feB[NKF * NC];
__device__ float4 g_feC[NKF * NC];
__device__ float2 g_feJ[NKF * NC];
// filter super composites
__device__ float4 g_sfA[NSF * NC];
__device__ float4 g_sfB[NSF * NC];
__device__ float4 g_sfC[NSF * NC];
__device__ float2 g_sfJ[NSF * NC];
// filter boundaries at 16-step granularity (filtered state at t = 16q - 1)
__device__ float2 g_fbM[NQS * NC];
__device__ float4 g_fbP[NQS * NC];
__device__ float2 g_fbM2[NSF * NC];
__device__ float4 g_fbP2[NSF * NC];
// filtered state at t = NT-1
__device__ float2 g_ffM[NC];
__device__ float4 g_ffP[NC];
// smoother sub-chunk composites (16 steps each): m' = M m + v ; Pvec' = L Pvec + w
__device__ float4 g_seM[NQS * NC];
__device__ float4 g_seV[NQS * NC];   // v0,v1,w0,w1
__device__ float4 g_seL1[NQS * NC];  // L00,L01,L02,L10
__device__ float4 g_seL2[NQS * NC];  // L11,L12,L20,L21
__device__ float2 g_seL3[NQS * NC];  // L22, w2
// smoother super composites
__device__ float4 g_ssM[NSF * NC];
__device__ float4 g_ssV[NSF * NC];
__device__ float4 g_ssL1[NSF * NC];
__device__ float4 g_ssL2[NSF * NC];
__device__ float2 g_ssL3[NSF * NC];
// smoother super boundaries
__device__ float2 g_sbM2[NSF * NC];
__device__ float4 g_sbP2[NSF * NC];

// ---------------- A(dt), Q(dt) ----------------
__device__ __forceinline__ void make_AQ(float dt, float lam, float s2,
    float &a11, float &a12, float &a21, float &a22,
    float &q00, float &q01, float &q11)
{
    float x  = lam * dt;
    float e  = __expf(-x);
    a11 = e * (1.0f + x);
    a12 = e * dt;
    a21 = -e * lam * x;
    a22 = e * (1.0f - x);
    float w  = 2.0f * x;
    float e2 = e * e;
    float poly = 1.0f/6.0f + w*(-1.0f/8.0f + w*(1.0f/20.0f + w*(-1.0f/72.0f + w*(1.0f/336.0f))));
    q00 = s2 * w * w * w * poly;
    q01 = 2.0f * s2 * lam * x * x * e2;
    q11 = s2 * lam * lam * (1.0f - e2 * (1.0f - w + 0.5f*w*w));
}

// ---------------- exact filter step ----------------
__device__ __forceinline__ float fstep(float &m0, float &m1,
                                       float &p00, float &p01, float &p11,
                                       float a11, float a12, float a21, float a22,
                                       float q00, float q01, float q11,
                                       float y, float r)
{
    float mp0 = fmaf(a11, m0, a12 * m1);
    float mp1 = fmaf(a21, m0, a22 * m1);
    float t00 = fmaf(a11, p00, a12 * p01);
    float t01 = fmaf(a11, p01, a12 * p11);
    float t10 = fmaf(a21, p00, a22 * p01);
    float t11 = fmaf(a21, p01, a22 * p11);
    float Pp00 = fmaf(t00, a11, fmaf(t01, a12, q00));
    float Pp01 = fmaf(t00, a21, fmaf(t01, a22, q01));
    float Pp11 = fmaf(t10, a21, fmaf(t11, a22, q11));
    float s   = Pp00 + r;
    float d   = y - mp0;
    float inv = __fdividef(1.0f, s + F_JITTER);
    float w0  = Pp00 * inv;
    float w1  = Pp01 * inv;
    m0  = fmaf(w0, d, mp0);
    m1  = fmaf(w1, d, mp1);
    p00 = fmaf(-w0, Pp00, Pp00);
    p01 = fmaf(-w0, Pp01, Pp01);
    p11 = fmaf(-w1, Pp01, Pp11);
    return fmaf(d * d, inv, __logf(s));
}

// ---------------- smoother gain quantities ----------------
__device__ __forceinline__ void sgain(float mf0, float mf1,
                                      float pf00, float pf01, float pf11,
                                      float a11, float a12, float a21, float a22,
                                      float q00, float q01, float q11,
                                      float &g00, float &g01, float &g10, float &g11,
                                      float &h0, float &h1,
                                      float &W00, float &W01, float &W11)
{
    float mp0 = fmaf(a11, mf0, a12 * mf1);
    float mp1 = fmaf(a21, mf0, a22 * mf1);
    float t00 = fmaf(a11, pf00, a12 * pf01);
    float t01 = fmaf(a11, pf01, a12 * pf11);
    float t10 = fmaf(a21, pf00, a22 * pf01);
    float t11 = fmaf(a21, pf01, a22 * pf11);
    float Pp00 = fmaf(t00, a11, fmaf(t01, a12, q00));
    float Pp01 = fmaf(t00, a21, fmaf(t01, a22, q01));
    float Pp11 = fmaf(t10, a21, fmaf(t11, a22, q11));
    float M00 = Pp00 + F_JITTER;
    float M11 = Pp11 + F_JITTER;
    float det = fmaf(M00, M11, -(Pp01 * Pp01));
    float di  = __fdividef(1.0f, det);
    float i00 =  M11 * di;
    float i01 = -Pp01 * di;
    float i11 =  M00 * di;
    g00 = fmaf(t00, i00, t10 * i01);
    g01 = fmaf(t00, i01, t10 * i11);
    g10 = fmaf(t01, i00, t11 * i01);
    g11 = fmaf(t01, i01, t11 * i11);
    h0 = mf0 - fmaf(g00, mp0, g01 * mp1);
    h1 = mf1 - fmaf(g10, mp0, g11 * mp1);
    float u00 = fmaf(g00, Pp00, g01 * Pp01);
    float u01 = fmaf(g00, Pp01, g01 * Pp11);
    float u10 = fmaf(g10, Pp00, g11 * Pp01);
    float u11 = fmaf(g10, Pp01, g11 * Pp11);
    W00 = pf00 + fmaf(u00, g00, u01 * g01);
    W01 = pf01 + fmaf(u00, g10, u01 * g11);
    W11 = pf11 + fmaf(u10, g10, u11 * g11);
}

// ---------------- filter element compose: E(earlier) (x) L(later) ----------------
__device__ __forceinline__ void fcompose(
    float &A00, float &A01, float &A10, float &A11,
    float &b0, float &b1, float &C00, float &C01, float &C11,
    float &e0, float &e1, float &J00, float &J01, float &J11,
    float lA00, float lA01, float lA10, float lA11,
    float lb0, float lb1, float lC00, float lC01, float lC11,
    float le0, float le1, float lJ00, float lJ01, float lJ11)
{
    float G00 = fmaf(C00, lJ00, fmaf(C01, lJ01, 1.0f));
    float G01 = fmaf(C00, lJ01, C01 * lJ11);
    float G10 = fmaf(C01, lJ00, C11 * lJ01);
    float G11 = fmaf(C01, lJ01, fmaf(C11, lJ11, 1.0f));
    float det = fmaf(G00, G11, -(G01 * G10));
    float id  = __fdividef(1.0f, det);
    float M00 =  G11 * id, M01 = -G01 * id, M10 = -G10 * id, M11 = G00 * id;
    float AM00 = fmaf(lA00, M00, lA01 * M10);
    float AM01 = fmaf(lA00, M01, lA01 * M11);
    float AM10 = fmaf(lA10, M00, lA11 * M10);
    float AM11 = fmaf(lA10, M01, lA11 * M11);
    float nA00 = fmaf(AM00, A00, AM01 * A10);
    float nA01 = fmaf(AM00, A01, AM01 * A11);
    float nA10 = fmaf(AM10, A00, AM11 * A10);
    float nA11 = fmaf(AM10, A01, AM11 * A11);
    float tb0 = fmaf(C00, le0, fmaf(C01, le1, b0));
    float tb1 = fmaf(C01, le0, fmaf(C11, le1, b1));
    float nb0 = fmaf(AM00, tb0, fmaf(AM01, tb1, lb0));
    float nb1 = fmaf(AM10, tb0, fmaf(AM11, tb1, lb1));
    float U00 = fmaf(AM00, C00, AM01 * C01);
    float U01 = fmaf(AM00, C01, AM01 * C11);
    float U10 = fmaf(AM10, C00, AM11 * C01);
    float U11 = fmaf(AM10, C01, AM11 * C11);
    float nC00 = fmaf(U00, lA00, fmaf(U01, lA01, lC00));
    float nC01 = fmaf(U00, lA10, fmaf(U01, lA11, lC01));
    float nC11 = fmaf(U10, lA10, fmaf(U11, lA11, lC11));
    float w0 = le0 - fmaf(lJ00, b0, lJ01 * b1);
    float w1 = le1 - fmaf(lJ01, b0, lJ11 * b1);
    float nw0 = fmaf(M00, w0, M10 * w1);
    float nw1 = fmaf(M01, w0, M11 * w1);
    float ne0 = fmaf(A00, nw0, fmaf(A10, nw1, e0));
    float ne1 = fmaf(A01, nw0, fmaf(A11, nw1, e1));
    float V00 = fmaf(M00, lJ00, M10 * lJ01);
    float V01 = fmaf(M00, lJ01, M10 * lJ11);
    float V10 = fmaf(M01, lJ00, M11 * lJ01);
    float V11 = fmaf(M01, lJ01, M11 * lJ11);
    float X00 = fmaf(A00, V00, A10 * V10);
    float X01 = fmaf(A00, V01, A10 * V11);
    float X10 = fmaf(A01, V00, A11 * V10);
    float X11 = fmaf(A01, V01, A11 * V11);
    float nJ00 = fmaf(X00, A00, fmaf(X01, A10, J00));
    float nJ01 = fmaf(X00, A01, fmaf(X01, A11, J01));
    float nJ11 = fmaf(X10, A01, fmaf(X11, A11, J11));
    A00=nA00; A01=nA01; A10=nA10; A11=nA11;
    b0=nb0; b1=nb1; C00=nC00; C01=nC01; C11=nC11;
    e0=ne0; e1=ne1; J00=nJ00; J01=nJ01; J11=nJ11;
}

// ---------------- filter element applied to a state ----------------
__device__ __forceinline__ void fapply(
    float &m0, float &m1, float &p0, float &p1, float &p2,
    float A00, float A01, float A10, float A11,
    float b0, float b1, float C00, float C01, float C11,
    float e0f, float e1f, float J00, float J01, float J11)
{
    float G00 = fmaf(p0, J00, fmaf(p1, J01, 1.0f));
    float G01 = fmaf(p0, J01, p1 * J11);
    float G10 = fmaf(p1, J00, p2 * J01);
    float G11 = fmaf(p1, J01, fmaf(p2, J11, 1.0f));
    float det = fmaf(G00, G11, -(G01 * G10));
    float id  = __fdividef(1.0f, det);
    float M00 =  G11 * id, M01 = -G01 * id, M10 = -G10 * id, M11 = G00 * id;
    float tb0 = fmaf(p0, e0f, fmaf(p1, e1f, m0));
    float tb1 = fmaf(p1, e0f, fmaf(p2, e1f, m1));
    float mt0 = fmaf(M00, tb0, M01 * tb1);
    float mt1 = fmaf(M10, tb0, M11 * tb1);
    float nm0 = fmaf(A00, mt0, fmaf(A01, mt1, b0));
    float nm1 = fmaf(A10, mt0, fmaf(A11, mt1, b1));
    float V00 = fmaf(M00, p0, M01 * p1);
    float V01 = fmaf(M00, p1, M01 * p2);
    float V10 = fmaf(M10, p0, M11 * p1);
    float V11 = fmaf(M10, p1, M11 * p2);
    float X00 = fmaf(A00, V00, A01 * V10);
    float X01 = fmaf(A00, V01, A01 * V11);
    float X10 = fmaf(A10, V00, A11 * V10);
    float X11 = fmaf(A10, V01, A11 * V11);
    float np0 = fmaf(X00, A00, fmaf(X01, A01, C00));
    float np1 = fmaf(X00, A10, fmaf(X01, A11, C01));
    float np2 = fmaf(X10, A10, fmaf(X11, A11, C11));
    m0 = nm0; m1 = nm1; p0 = np0; p1 = np1; p2 = np2;
}

// ---------------- smoother affine apply ----------------
__device__ __forceinline__ void sapply(
    float &m0, float &m1, float &p0, float &p1, float &p2,
    float4 sM, float4 sV, float4 s1, float4 s2, float2 s3)
{
    float nm0 = fmaf(sM.x, m0, fmaf(sM.y, m1, sV.x));
    float nm1 = fmaf(sM.z, m0, fmaf(sM.w, m1, sV.y));
    float np0 = fmaf(s1.x, p0, fmaf(s1.y, p1, fmaf(s1.z, p2, sV.z)));
    float np1 = fmaf(s1.w, p0, fmaf(s2.x, p1, fmaf(s2.y, p2, sV.w)));
    float np2 = fmaf(s2.z, p0, fmaf(s2.w, p1, fmaf(s3.x, p2, s3.y)));
    m0 = nm0; m1 = nm1; p0 = np0; p1 = np1; p2 = np2;
}

// ================= F2: filter chunk composites =================
__global__ void __launch_bounds__(256) fscan_chunk(
    const float* __restrict__ dtn,
    const float* __restrict__ ys,
    const float* __restrict__ rs,
    const float* __restrict__ ls,
    const float* __restrict__ vs)
{
    int c = blockIdx.y * 256 + threadIdx.x;
    int k = blockIdx.x;
    int v = c >> 4, l = c & 15;
    float lam = SQRT3 / ls[l];
    float s2  = vs[l];
    const float* yp = ys + (size_t)v * NT * NL + l;
    const float* rp = rs + (size_t)v * NT * NL + l;
    const float* dp = dtn + (size_t)v * NT1;

    float A00=1.f, A01=0.f, A10=0.f, A11=1.f;
    float b0=0.f, b1=0.f;
    float C00=0.f, C01=0.f, C11=0.f;
    float e0=0.f, e1=0.f;
    float J00=0.f, J01=0.f, J11=0.f;

    int tlo = (k == 0) ? 1 : CHF * k;
    int thi = CHF * k + CHF;
    for (int t = tlo; t < thi; ++t) {
        float dt = dp[t - 1];
        float y  = yp[(size_t)t * NL];
        float r  = rp[(size_t)t * NL];
        float a11,a12,a21,a22,q00,q01,q11;
        make_AQ(dt, lam, s2, a11,a12,a21,a22, q00,q01,q11);
        float S  = q00 + r;
        float iS = __fdividef(1.0f, S);
        float k0 = q00 * iS;
        float k1 = q01 * iS;
        float om = 1.0f - k0;
        float lA00 = om * a11, lA01 = om * a12;
        float lA10 = a21 - k1 * a11, lA11 = a22 - k1 * a12;
        float lb0 = k0 * y, lb1 = k1 * y;
        float lC00 = om * q00, lC01 = om * q01, lC11 = q11 - k1 * q01;
        float ySi = y * iS;
        float le0 = a11 * ySi, le1 = a12 * ySi;
        float lJ00 = a11 * a11 * iS, lJ01 = a11 * a12 * iS, lJ11 = a12 * a12 * iS;
        fcompose(A00,A01,A10,A11,b0,b1,C00,C01,C11,e0,e1,J00,J01,J11,
                 lA00,lA01,lA10,lA11,lb0,lb1,lC00,lC01,lC11,le0,le1,lJ00,lJ01,lJ11);
    }
    int ix = k * NC + c;
    g_feA[ix] = make_float4(A00, A01, A10, A11);
    g_feB[ix] = make_float4(b0, b1, e0, e1);
    g_feC[ix] = make_float4(C00, C01, C11, J00);
    g_feJ[ix] = make_float2(J01, J11);
}

// ================= F2b: compose 16 chunks -> super composites =================
__global__ void __launch_bounds__(512) fcarry1()
{
    int c = threadIdx.x;
    int s = blockIdx.x;
    float A00=1.f, A01=0.f, A10=0.f, A11=1.f;
    float b0=0.f, b1=0.f, C00=0.f, C01=0.f, C11=0.f;
    float e0=0.f, e1=0.f, J00=0.f, J01=0.f, J11=0.f;
    int base = (s * 16) * NC + c;
    #pragma unroll 4
    for (int j = 0; j < 16; ++j) {
        int ix = base + j * NC;
        float4 fA = g_feA[ix], fB = g_feB[ix], fC = g_feC[ix];
        float2 fJ = g_feJ[ix];
        fcompose(A00,A01,A10,A11,b0,b1,C00,C01,C11,e0,e1,J00,J01,J11,
                 fA.x,fA.y,fA.z,fA.w, fB.x,fB.y, fC.x,fC.y,fC.z,
                 fB.z,fB.w, fC.w,fJ.x,fJ.y);
    }
    int ox = s * NC + c;
    g_sfA[ox] = make_float4(A00, A01, A10, A11);
    g_sfB[ox] = make_float4(b0, b1, e0, e1);
    g_sfC[ox] = make_float4(C00, C01, C11, J00);
    g_sfJ[ox] = make_float2(J01, J11);
}

// ================= F3a: serial scan over 16 supers =================
__global__ void __launch_bounds__(512) fcarry2(
    const float* __restrict__ ys,
    const float* __restrict__ rs,
    const float* __restrict__ ls,
    const float* __restrict__ vs)
{
    int c = threadIdx.x;
    int v = c >> 4, l = c & 15;
    float lam = SQRT3 / ls[l];
    float s2  = vs[l];
    float y0 = ys[(size_t)v * NT * NL + l];
    float r0 = rs[(size_t)v * NT * NL + l];
    float s  = s2 + r0;
    float inv = __fdividef(1.0f, s + F_JITTER);
    float w0 = s2 * inv;
    float m0 = w0 * y0, m1 = 0.0f;
    float p0 = s2 - w0 * s2, p1 = 0.0f, p2 = s2 * lam * lam;

    #pragma unroll
    for (int ss = 0; ss < NSF; ++ss) {
        int ix = ss * NC + c;
        g_fbM2[ix] = make_float2(m0, m1);
        g_fbP2[ix] = make_float4(p0, p1, p2, 0.0f);
        float4 fA = g_sfA[ix], fB = g_sfB[ix], fC = g_sfC[ix];
        float2 fJ = g_sfJ[ix];
        fapply(m0,m1,p0,p1,p2,
               fA.x,fA.y,fA.z,fA.w, fB.x,fB.y, fC.x,fC.y,fC.z,
               fB.z,fB.w, fC.w,fJ.x,fJ.y);
    }
    g_ffM[c] = make_float2(m0, m1);
    g_ffP[c] = make_float4(p0, p1, p2, 0.0f);
}

// ================= F4/S2 fused: expand + re-filter + log-lik + smoother sub-composites =================
__global__ void __launch_bounds__(256) fsmcomp(
    const float* __restrict__ dtn,
    const float* __restrict__ ys,
    const float* __restrict__ rs,
    const float* __restrict__ ls,
    const float* __restrict__ vs)
{
    int c = blockIdx.y * 256 + threadIdx.x;
    int k = blockIdx.x;
    int v = c >> 4, l = c & 15;
    float lam = SQRT3 / ls[l];
    float s2  = vs[l];
    const float* yp = ys + (size_t)v * NT * NL + l;
    const float* rp = rs + (size_t)v * NT * NL + l;
    const float* dp = dtn + (size_t)v * NT1;

    // smoother composite accumulator (identity)
    float M00=1.f, M01=0.f, M10=0.f, M11=1.f, v0=0.f, v1=0.f;
    float L00=1.f, L01=0.f, L02=0.f;
    float L10=0.f, L11=1.f, L12=0.f;
    float L20=0.f, L21=0.f, L22=1.f;
    float w0=0.f, w1=0.f, w2=0.f;

    float m0, m1, p0, p1, p2;
    float a11,a12,a21,a22,q00,q01,q11;  // AQ for transition INTO next step (carried)
    float acc = 0.0f;

#define RCOMPOSE() { \
    float g00,g01,g10,g11,h0,h1,W00,W01,W11; \
    sgain(m0, m1, p0, p1, p2, a11,a12,a21,a22, q00,q01,q11, \
          g00,g01,g10,g11, h0,h1, W00,W01,W11); \
    float T00 = g00*g00, T01 = 2.0f*g00*g01, T02 = g01*g01; \
    float T10 = g00*g10, T11 = fmaf(g00,g11, g01*g10), T12 = g01*g11; \
    float T20 = g10*g10, T21 = 2.0f*g10*g11, T22 = g11*g11; \
    float nM00 = fmaf(M00, g00, M01 * g10); \
    float nM01 = fmaf(M00, g01, M01 * g11); \
    float nM10 = fmaf(M10, g00, M11 * g10); \
    float nM11 = fmaf(M10, g01, M11 * g11); \
    float nv0 = fmaf(M00, h0, fmaf(M01, h1, v0)); \
    float nv1 = fmaf(M10, h0, fmaf(M11, h1, v1)); \
    float nL00 = -fmaf(L00, T00, fmaf(L01, T10, L02 * T20)); \
    float nL01 = -fmaf(L00, T01, fmaf(L01, T11, L02 * T21)); \
    float nL02 = -fmaf(L00, T02, fmaf(L01, T12, L02 * T22)); \
    float nL10 = -fmaf(L10, T00, fmaf(L11, T10, L12 * T20)); \
    float nL11 = -fmaf(L10, T01, fmaf(L11, T11, L12 * T21)); \
    float nL12 = -fmaf(L10, T02, fmaf(L11, T12, L12 * T22)); \
    float nL20 = -fmaf(L20, T00, fmaf(L21, T10, L22 * T20)); \
    float nL21 = -fmaf(L20, T01, fmaf(L21, T11, L22 * T21)); \
    float nL22 = -fmaf(L20, T02, fmaf(L21, T12, L22 * T22)); \
    float nw0 = fmaf(L00, W00, fmaf(L01, W01, fmaf(L02, W11, w0))); \
    float nw1 = fmaf(L10, W00, fmaf(L11, W01, fmaf(L12, W11, w1))); \
    float nw2 = fmaf(L20, W00, fmaf(L21, W01, fmaf(L22, W11, w2))); \
    M00=nM00; M01=nM01; M10=nM10; M11=nM11; v0=nv0; v1=nv1; \
    L00=nL00; L01=nL01; L02=nL02; L10=nL10; L11=nL11; L12=nL12; \
    L20=nL20; L21=nL21; L22=nL22; w0=nw0; w1=nw1; w2=nw2; }

#define STORE_SE(qq) { \
    int sx = (qq) * NC + c; \
    g_seM[sx]  = make_float4(M00, M01, M10, M11); \
    g_seV[sx]  = make_float4(v0, v1, w0, w1); \
    g_seL1[sx] = make_float4(L00, L01, L02, L10); \
    g_seL2[sx] = make_float4(L11, L12, L20, L21); \
    g_seL3[sx] = make_float2(L22, w2); \
    M00=1.f; M01=0.f; M10=0.f; M11=1.f; v0=0.f; v1=0.f; \
    L00=1.f; L01=0.f; L02=0.f; L10=0.f; L11=1.f; L12=0.f; \
    L20=0.f; L21=0.f; L22=1.f; w0=0.f; w1=0.f; w2=0.f; }

    int tlo;
    if (k == 0) {
        float y = yp[0], r = rp[0];
        float s = s2 + r;
        float inv = __fdividef(1.0f, s + F_JITTER);
        float wk = s2 * inv;
        m0 = wk * y; m1 = 0.0f;
        p0 = s2 - wk * s2; p1 = 0.0f; p2 = s2 * lam * lam;
        acc = fmaf(y * y, inv, __logf(s));
        make_AQ(dp[0], lam, s2, a11,a12,a21,a22, q00,q01,q11);
        RCOMPOSE();   // element t = 0
        tlo = 1;
    } else {
        // expand chunk boundary from super boundary
        int s = k >> 4;
        float2 bm = g_fbM2[s * NC + c];
        float4 bp = g_fbP2[s * NC + c];
        m0 = bm.x; m1 = bm.y; p0 = bp.x; p1 = bp.y; p2 = bp.z;
        for (int jj = s * 16; jj < k; ++jj) {
            int nx = jj * NC + c;
            float4 fA = g_feA[nx], fB = g_feB[nx], fC = g_feC[nx];
            float2 fJ = g_feJ[nx];
            fapply(m0,m1,p0,p1,p2,
                   fA.x,fA.y,fA.z,fA.w, fB.x,fB.y, fC.x,fC.y,fC.z,
                   fB.z,fB.w, fC.w,fJ.x,fJ.y);
        }
        // publish 16-step boundary q = 2k (filtered at t = 32k - 1)
        g_fbM[(2 * k) * NC + c] = make_float2(m0, m1);
        g_fbP[(2 * k) * NC + c] = make_float4(p0, p1, p2, 0.0f);
        make_AQ(dp[CHF*k - 1], lam, s2, a11,a12,a21,a22, q00,q01,q11);
        tlo = CHF * k;
    }
    int thi = (k == NKF - 1) ? (NT - 1) : (CHF * k + CHF);   // exclusive
    for (int t = tlo; t < thi; ++t) {
        float y = yp[(size_t)t * NL];
        float r = rp[(size_t)t * NL];
        acc += fstep(m0, m1, p0, p1, p2, a11,a12,a21,a22, q00,q01,q11, y, r);
        if ((t & 31) == 15) {
            // publish 16-step boundary q = (t+1)/16 (odd q only; even from entry)
            int qb = (t + 1) >> 4;
            g_fbM[qb * NC + c] = make_float2(m0, m1);
            g_fbP[qb * NC + c] = make_float4(p0, p1, p2, 0.0f);
        }
        make_AQ(dp[t], lam, s2, a11,a12,a21,a22, q00,q01,q11);
        RCOMPOSE();   // element t
        if ((t & 15) == 15) STORE_SE(t >> 4);
    }
    if (k == NKF - 1) {
        // final filter step t = NT-1 (log-lik only; no smoother element there)
        acc += fstep(m0, m1, p0, p1, p2, a11,a12,a21,a22, q00,q01,q11,
                     yp[(size_t)(NT - 1) * NL], rp[(size_t)(NT - 1) * NL]);
        STORE_SE(NQS - 1);   // composite of elements 8176..8190
    }
#undef RCOMPOSE
#undef STORE_SE
    g_lpp[k * NC + c] = acc;
}

// ================= S2b: compose 32 smoother sub-chunks -> super =================
__global__ void __launch_bounds__(512) scarry1()
{
    int c = threadIdx.x;
    int s = blockIdx.x;
    float M00=1.f, M01=0.f, M10=0.f, M11=1.f, v0=0.f, v1=0.f;
    float L00=1.f, L01=0.f, L02=0.f;
    float L10=0.f, L11=1.f, L12=0.f;
    float L20=0.f, L21=0.f, L22=1.f;
    float w0=0.f, w1=0.f, w2=0.f;
    int base = s * 32 * NC + c;
    #pragma unroll 4
    for (int j = 31; j >= 0; --j) {
        int ix = base + j * NC;
        float4 eM = g_seM[ix], eV = g_seV[ix];
        float4 e1 = g_seL1[ix], e2 = g_seL2[ix];
        float2 e3 = g_seL3[ix];
        float nM00 = fmaf(eM.x, M00, eM.y * M10);
        float nM01 = fmaf(eM.x, M01, eM.y * M11);
        float nM10 = fmaf(eM.z, M00, eM.w * M10);
        float nM11 = fmaf(eM.z, M01, eM.w * M11);
        float nv0 = fmaf(eM.x, v0, fmaf(eM.y, v1, eV.x));
        float nv1 = fmaf(eM.z, v0, fmaf(eM.w, v1, eV.y));
        float E00=e1.x, E01=e1.y, E02=e1.z, E10=e1.w, E11=e2.x, E12=e2.y;
        float E20=e2.z, E21=e2.w, E22=e3.x;
        float a0 = fmaf(E00, L00, fmaf(E01, L10, E02 * L20));
        float a1 = fmaf(E00, L01, fmaf(E01, L11, E02 * L21));
        float a2 = fmaf(E00, L02, fmaf(E01, L12, E02 * L22));
        float bb0 = fmaf(E10, L00, fmaf(E11, L10, E12 * L20));
        float bb1 = fmaf(E10, L01, fmaf(E11, L11, E12 * L21));
        float bb2 = fmaf(E10, L02, fmaf(E11, L12, E12 * L22));
        float cc0 = fmaf(E20, L00, fmaf(E21, L10, E22 * L20));
        float cc1 = fmaf(E20, L01, fmaf(E21, L11, E22 * L21));
        float cc2 = fmaf(E20, L02, fmaf(E21, L12, E22 * L22));
        float nw0 = fmaf(E00, w0, fmaf(E01, w1, fmaf(E02, w2, eV.z)));
        float nw1 = fmaf(E10, w0, fmaf(E11, w1, fmaf(E12, w2, eV.w)));
        float nw2 = fmaf(E20, w0, fmaf(E21, w1, fmaf(E22, w2, e3.y)));
        M00=nM00; M01=nM01; M10=nM10; M11=nM11; v0=nv0; v1=nv1;
        L00=a0; L01=a1; L02=a2; L10=bb0; L11=bb1; L12=bb2; L20=cc0; L21=cc1; L22=cc2;
        w0=nw0; w1=nw1; w2=nw2;
    }
    int ox = s * NC + c;
    g_ssM[ox]  = make_float4(M00, M01, M10, M11);
    g_ssV[ox]  = make_float4(v0, v1, w0, w1);
    g_ssL1[ox] = make_float4(L00, L01, L02, L10);
    g_ssL2[ox] = make_float4(L11, L12, L20, L21);
    g_ssL3[ox] = make_float2(L22, w2);
}

// ================= S3a: serial scan over 16 supers (backward) =================
__global__ void __launch_bounds__(512) scarry2()
{
    int c = threadIdx.x;
    float2 fm = g_ffM[c];
    float4 fp = g_ffP[c];
    float m0 = fm.x, m1 = fm.y;
    float p0 = fp.x, p1 = fp.y, p2 = fp.z;
    #pragma unroll
    for (int s = NSF - 1; s >= 0; --s) {
        int ix = s * NC + c;
        g_sbM2[ix] = make_float2(m0, m1);
        g_sbP2[ix] = make_float4(p0, p1, p2, 0.0f);
        sapply(m0, m1, p0, p1, p2,
               g_ssM[ix], g_ssV[ix], g_ssL1[ix], g_ssL2[ix], g_ssL3[ix]);
    }
}

// ================= SOLVE: 16-step tiles, re-filter + re-smooth + outputs =================
// grid (NQS, 4), block 128, dynamic smem = SOLVE_SMEM
__global__ void __launch_bounds__(128) solve_kernel(
    const float* __restrict__ dtn,
    const float* __restrict__ ys,
    const float* __restrict__ rs,
    const float* __restrict__ ls,
    const float* __restrict__ vs,
    float* __restrict__ out)
{
    extern __shared__ char sh[];
    float2* sm = (float2*)sh;                    // [128][17]
    float4* sp = (float4*)(sh + 128 * 17 * 8);   // [128][17]
#define SM(ch, tl) sm[(ch) * 17 + (tl)]
#define SP(ch, tl) sp[(ch) * 17 + (tl)]

    int tid = threadIdx.x;
    int q = blockIdx.x;
    int cbase = blockIdx.y * 128;
    int c = cbase + tid;
    int v = c >> 4, l = c & 15;
    float lam = SQRT3 / ls[l];
    float s2  = vs[l];
    const float* yp = ys + (size_t)v * NT * NL + l;
    const float* rp = rs + (size_t)v * NT * NL + l;
    const float* dp = dtn + (size_t)v * NT1;
    int t0 = CHS * q;

    // ---- forward: exact filter over sub-chunk, fill smem tile ----
    float m0, m1, p0, p1, p2;
    int tlo;
    if (q == 0) {
        float y = yp[0], r = rp[0];
        float s = s2 + r;
        float inv = __fdividef(1.0f, s + F_JITTER);
        float w0 = s2 * inv;
        m0 = w0 * y; m1 = 0.0f;
        p0 = s2 - w0 * s2; p1 = 0.0f; p2 = s2 * lam * lam;
        SM(tid, 0) = make_float2(m0, m1);
        SP(tid, 0) = make_float4(p0, p1, p1, p2);
        tlo = 1;
    } else {
        float2 bm = g_fbM[q * NC + c];
        float4 bp = g_fbP[q * NC + c];
        m0 = bm.x; m1 = bm.y; p0 = bp.x; p1 = bp.y; p2 = bp.z;
        tlo = t0;
    }
    for (int t = tlo; t < t0 + CHS; ++t) {
        float a11,a12,a21,a22,q00,q01,q11;
        make_AQ(dp[t - 1], lam, s2, a11,a12,a21,a22, q00,q01,q11);
        fstep(m0, m1, p0, p1, p2, a11,a12,a21,a22, q00,q01,q11,
              yp[(size_t)t * NL], rp[(size_t)t * NL]);
        int tl = t - t0;
        SM(tid, tl) = make_float2(m0, m1);
        SP(tid, tl) = make_float4(p0, p1, p1, p2);
    }
    __syncthreads();

    // ---- bulk write filtered m (8 float4 per row) ----
    {
        float4* om4 = (float4*)out;
        int sub = tid & 7, grp = tid >> 3;
        #pragma unroll
        for (int rep = 0; rep < 8; ++rep) {
            int ch = rep * 16 + grp;
            size_t rowb = ((size_t)(cbase + ch) * NT + t0) >> 1;  // float4 units
            float2 a = SM(ch, sub * 2), b = SM(ch, sub * 2 + 1);
            om4[rowb + sub] = make_float4(a.x, a.y, b.x, b.y);
        }
        // ---- bulk write filtered P (16 float4 per row) ----
        float4* op = (float4*)(out + OFF_P);
        int sub16 = tid & 15, grp16 = tid >> 4;
        #pragma unroll
        for (int rep = 0; rep < 16; ++rep) {
            int ch = rep * 8 + grp16;
            size_t rowb = (size_t)(cbase + ch) * NT + t0;   // float4 units
            op[rowb + sub16] = SP(ch, sub16);
        }
    }
    __syncthreads();

    // ---- expand smoothed boundary from super boundary, then backward ----
    {
        int s = q >> 5;
        float2 bm = g_sbM2[s * NC + c];
        float4 bp = g_sbP2[s * NC + c];
        float ms0 = bm.x, ms1 = bm.y;
        float s00 = bp.x, s01 = bp.y, s11 = bp.z;
        for (int jj = s * 32 + 31; jj > q; --jj) {
            int ix = jj * NC + c;
            sapply(ms0, ms1, s00, s01, s11,
                   g_seM[ix], g_seV[ix], g_seL1[ix], g_seL2[ix], g_seL3[ix]);
        }
        int tstart;
        if (q == NQS - 1) {
            SM(tid, CHS - 1) = make_float2(ms0, s00);   // t = NT-1: smoothed == filtered
            tstart = NT - 2;
        } else {
            tstart = t0 + CHS - 1;
        }
        for (int t = tstart; t >= t0; --t) {
            int tl = t - t0;
            float2 mf = SM(tid, tl);
            float4 pf = SP(tid, tl);
            float a11,a12,a21,a22,q00,q01,q11;
            make_AQ(dp[t], lam, s2, a11,a12,a21,a22, q00,q01,q11);
            float g00,g01,g10,g11,h0,h1,W00,W01,W11;
            sgain(mf.x, mf.y, pf.x, pf.y, pf.w, a11,a12,a21,a22, q00,q01,q11,
                  g00,g01,g10,g11, h0,h1, W00,W01,W11);
            float u00 = fmaf(g00, s00, g01 * s01);
            float u01 = fmaf(g00, s01, g01 * s11);
            float u10 = fmaf(g10, s00, g11 * s01);
            float u11 = fmaf(g10, s01, g11 * s11);
            float nm0 = fmaf(g00, ms0, fmaf(g01, ms1, h0));
            float nm1 = fmaf(g10, ms0, fmaf(g11, ms1, h1));
            s00 = W00 - fmaf(u00, g00, u01 * g01);
            s01 = W01 - fmaf(u00, g10, u01 * g11);
            s11 = W11 - fmaf(u10, g10, u11 * g11);
            ms0 = nm0; ms1 = nm1;
            SM(tid, tl) = make_float2(ms0, s00);
        }
    }
    __syncthreads();

    // ---- bulk write mz, pz (4 float4 per row each) ----
    {
        float* omz = out + OFF_MZ;
        float* opz = out + OFF_PZ;
        int sub = tid & 3, grp = tid >> 2;
        #pragma unroll
        for (int rep = 0; rep < 4; ++rep) {
            int ch = rep * 32 + grp;
            size_t rowb = (size_t)(cbase + ch) * NT + t0;   // float units
            float2 e0 = SM(ch, sub * 4 + 0);
            float2 e1 = SM(ch, sub * 4 + 1);
            float2 e2 = SM(ch, sub * 4 + 2);
            float2 e3 = SM(ch, sub * 4 + 3);
            ((float4*)(omz + rowb))[sub] = make_float4(e0.x, e1.x, e2.x, e3.x);
            ((float4*)(opz + rowb))[sub] = make_float4(e0.y, e1.y, e2.y, e3.y);
        }
    }
#undef SM
#undef SP
}

// ---------------- deterministic log-lik reduction ----------------
__global__ void __launch_bounds__(512) logp_kernel(float* __restrict__ out)
{
    __shared__ double sh[NC];
    int c = threadIdx.x;
    double a = 0.0;
    #pragma unroll 4
    for (int k = 0; k < NKF; ++k) a += (double)g_lpp[k * NC + c];
    sh[c] = -0.5 * (a + (double)NT * (double)F_LOG2PI);
    __syncthreads();
    if (c < NV) {
        double s = 0.0;
        #pragma unroll
        for (int l = 0; l < NL; ++l) s += sh[c * NL + l];
        out[OFF_LP + c] = (float)s;
    }
}

extern "C" void kernel_launch(void* const* d_in, const int* in_sizes, int n_in,
                              void* d_out, int out_size)
{
    const float* dtn = (const float*)d_in[0];
    const float* ys  = (const float*)d_in[1];
    const float* rs  = (const float*)d_in[2];
    const float* ls  = (const float*)d_in[3];
    const float* vs  = (const float*)d_in[4];
    float* out = (float*)d_out;

    cudaFuncSetAttribute(solve_kernel,
                         cudaFuncAttributeMaxDynamicSharedMemorySize, SOLVE_SMEM);

    fscan_chunk<<<dim3(NKF, 2), 256>>>(dtn, ys, rs, ls, vs);
    fcarry1<<<NSF, 512>>>();
    fcarry2<<<1, 512>>>(ys, rs, ls, vs);
    fsmcomp<<<dim3(NKF, 2), 256>>>(dtn, ys, rs, ls, vs);
    scarry1<<<NSF, 512>>>();
    scarry2<<<1, 512>>>();
    solve_kernel<<<dim3(NQS, 4), 128, SOLVE_SMEM>>>(dtn, ys, rs, ls, vs, out);
    logp_kernel<<<1, 512>>>(out);
}

// round 16
// speedup vs baseline: 1.1066x; 1.1066x over previous
#include <cuda_runtime.h>

#define NV 32
#define NT 8192
#define NT1 8191
#define NL 16
#define NC 512
#define NKF 256    /* filter chunks of 32 steps */
#define CHF 32
#define NSF 16     /* supers of 16 chunks (512 steps) */
#define NQS 512    /* solve sub-chunks of 16 steps */
#define CHS 16

#define OFF_P  8388608u
#define OFF_MZ 25165824u
#define OFF_PZ 29360128u
#define OFF_LP 33554432u

#define F_JITTER 1e-6f
#define F_LOG2PI 1.8378770664093453f
#define SQRT3    1.7320508075688772f

#define SOLVE_SMEM (128*17*8 + 128*17*16)

__device__ float  g_lpp[NKF * NC];
// filter chunk composites (A, b, C, eta, J)
__device__ float4 g_feA[NKF * NC];
__device__ float4 g_feB[NKF * NC];
__device__ float4 g_feC[NKF * NC];
__device__ float2 g_feJ[NKF * NC];
// filter super composites
__device__ float4 g_sfA[NSF * NC];
__device__ float4 g_sfB[NSF * NC];
__device__ float4 g_sfC[NSF * NC];
__device__ float2 g_sfJ[NSF * NC];
// filter boundaries at 16-step granularity (filtered state at t = 16q - 1)
__device__ float2 g_fbM[NQS * NC];
__device__ float4 g_fbP[NQS * NC];
__device__ float2 g_fbM2[NSF * NC];
__device__ float4 g_fbP2[NSF * NC];
// filtered state at t = NT-1
__device__ float2 g_ffM[NC];
__device__ float4 g_ffP[NC];
// smoother sub-chunk composites (16 steps): m' = M m + v ; P' = Wc + s*Gc P Gc^T
__device__ float4 g_seM[NQS * NC];   // M00,M01,M10,M11
__device__ float4 g_seV[NQS * NC];   // v0,v1,Wc00,Wc01
__device__ float4 g_seG[NQS * NC];   // Gc00,Gc01,Gc10,Gc11
__device__ float2 g_seW[NQS * NC];   // Wc11, sign
// smoother super composites
__device__ float4 g_ssM[NSF * NC];
__device__ float4 g_ssV[NSF * NC];
__device__ float4 g_ssG[NSF * NC];
__device__ float2 g_ssW[NSF * NC];
// smoother super boundaries
__device__ float2 g_sbM2[NSF * NC];
__device__ float4 g_sbP2[NSF * NC];

// ---------------- A(dt), Q(dt) ----------------
__device__ __forceinline__ void make_AQ(float dt, float lam, float s2,
    float &a11, float &a12, float &a21, float &a22,
    float &q00, float &q01, float &q11)
{
    float x  = lam * dt;
    float e  = __expf(-x);
    a11 = e * (1.0f + x);
    a12 = e * dt;
    a21 = -e * lam * x;
    a22 = e * (1.0f - x);
    float w  = 2.0f * x;
    float e2 = e * e;
    float poly = 1.0f/6.0f + w*(-1.0f/8.0f + w*(1.0f/20.0f + w*(-1.0f/72.0f + w*(1.0f/336.0f))));
    q00 = s2 * w * w * w * poly;
    q01 = 2.0f * s2 * lam * x * x * e2;
    q11 = s2 * lam * lam * (1.0f - e2 * (1.0f - w + 0.5f*w*w));
}

// ---------------- exact filter step ----------------
__device__ __forceinline__ float fstep(float &m0, float &m1,
                                       float &p00, float &p01, float &p11,
                                       float a11, float a12, float a21, float a22,
                                       float q00, float q01, float q11,
                                       float y, float r)
{
    float mp0 = fmaf(a11, m0, a12 * m1);
    float mp1 = fmaf(a21, m0, a22 * m1);
    float t00 = fmaf(a11, p00, a12 * p01);
    float t01 = fmaf(a11, p01, a12 * p11);
    float t10 = fmaf(a21, p00, a22 * p01);
    float t11 = fmaf(a21, p01, a22 * p11);
    float Pp00 = fmaf(t00, a11, fmaf(t01, a12, q00));
    float Pp01 = fmaf(t00, a21, fmaf(t01, a22, q01));
    float Pp11 = fmaf(t10, a21, fmaf(t11, a22, q11));
    float s   = Pp00 + r;
    float d   = y - mp0;
    float inv = __fdividef(1.0f, s + F_JITTER);
    float w0  = Pp00 * inv;
    float w1  = Pp01 * inv;
    m0  = fmaf(w0, d, mp0);
    m1  = fmaf(w1, d, mp1);
    p00 = fmaf(-w0, Pp00, Pp00);
    p01 = fmaf(-w0, Pp01, Pp01);
    p11 = fmaf(-w1, Pp01, Pp11);
    return fmaf(d * d, inv, __logf(s));
}

// ---------------- smoother gain quantities (standalone, used in solve) ----------------
__device__ __forceinline__ void sgain(float mf0, float mf1,
                                      float pf00, float pf01, float pf11,
                                      float a11, float a12, float a21, float a22,
                                      float q00, float q01, float q11,
                                      float &g00, float &g01, float &g10, float &g11,
                                      float &h0, float &h1,
                                      float &W00, float &W01, float &W11)
{
    float mp0 = fmaf(a11, mf0, a12 * mf1);
    float mp1 = fmaf(a21, mf0, a22 * mf1);
    float t00 = fmaf(a11, pf00, a12 * pf01);
    float t01 = fmaf(a11, pf01, a12 * pf11);
    float t10 = fmaf(a21, pf00, a22 * pf01);
    float t11 = fmaf(a21, pf01, a22 * pf11);
    float Pp00 = fmaf(t00, a11, fmaf(t01, a12, q00));
    float Pp01 = fmaf(t00, a21, fmaf(t01, a22, q01));
    float Pp11 = fmaf(t10, a21, fmaf(t11, a22, q11));
    float M00 = Pp00 + F_JITTER;
    float M11 = Pp11 + F_JITTER;
    float det = fmaf(M00, M11, -(Pp01 * Pp01));
    float di  = __fdividef(1.0f, det);
    float i00 =  M11 * di;
    float i01 = -Pp01 * di;
    float i11 =  M00 * di;
    g00 = fmaf(t00, i00, t10 * i01);
    g01 = fmaf(t00, i01, t10 * i11);
    g10 = fmaf(t01, i00, t11 * i01);
    g11 = fmaf(t01, i01, t11 * i11);
    h0 = mf0 - fmaf(g00, mp0, g01 * mp1);
    h1 = mf1 - fmaf(g10, mp0, g11 * mp1);
    float u00 = fmaf(g00, Pp00, g01 * Pp01);
    float u01 = fmaf(g00, Pp01, g01 * Pp11);
    float u10 = fmaf(g10, Pp00, g11 * Pp01);
    float u11 = fmaf(g10, Pp01, g11 * Pp11);
    W00 = pf00 + fmaf(u00, g00, u01 * g01);
    W01 = pf01 + fmaf(u00, g10, u01 * g11);
    W11 = pf11 + fmaf(u10, g10, u11 * g11);
}

// ---------------- filter element compose: E(earlier) (x) L(later) ----------------
__device__ __forceinline__ void fcompose(
    float &A00, float &A01, float &A10, float &A11,
    float &b0, float &b1, float &C00, float &C01, float &C11,
    float &e0, float &e1, float &J00, float &J01, float &J11,
    float lA00, float lA01, float lA10, float lA11,
    float lb0, float lb1, float lC00, float lC01, float lC11,
    float le0, float le1, float lJ00, float lJ01, float lJ11)
{
    float G00 = fmaf(C00, lJ00, fmaf(C01, lJ01, 1.0f));
    float G01 = fmaf(C00, lJ01, C01 * lJ11);
    float G10 = fmaf(C01, lJ00, C11 * lJ01);
    float G11 = fmaf(C01, lJ01, fmaf(C11, lJ11, 1.0f));
    float det = fmaf(G00, G11, -(G01 * G10));
    float id  = __fdividef(1.0f, det);
    float M00 =  G11 * id, M01 = -G01 * id, M10 = -G10 * id, M11 = G00 * id;
    float AM00 = fmaf(lA00, M00, lA01 * M10);
    float AM01 = fmaf(lA00, M01, lA01 * M11);
    float AM10 = fmaf(lA10, M00, lA11 * M10);
    float AM11 = fmaf(lA10, M01, lA11 * M11);
    float nA00 = fmaf(AM00, A00, AM01 * A10);
    float nA01 = fmaf(AM00, A01, AM01 * A11);
    float nA10 = fmaf(AM10, A00, AM11 * A10);
    float nA11 = fmaf(AM10, A01, AM11 * A11);
    float tb0 = fmaf(C00, le0, fmaf(C01, le1, b0));
    float tb1 = fmaf(C01, le0, fmaf(C11, le1, b1));
    float nb0 = fmaf(AM00, tb0, fmaf(AM01, tb1, lb0));
    float nb1 = fmaf(AM10, tb0, fmaf(AM11, tb1, lb1));
    float U00 = fmaf(AM00, C00, AM01 * C01);
    float U01 = fmaf(AM00, C01, AM01 * C11);
    float U10 = fmaf(AM10, C00, AM11 * C01);
    float U11 = fmaf(AM10, C01, AM11 * C11);
    float nC00 = fmaf(U00, lA00, fmaf(U01, lA01, lC00));
    float nC01 = fmaf(U00, lA10, fmaf(U01, lA11, lC01));
    float nC11 = fmaf(U10, lA10, fmaf(U11, lA11, lC11));
    float w0 = le0 - fmaf(lJ00, b0, lJ01 * b1);
    float w1 = le1 - fmaf(lJ01, b0, lJ11 * b1);
    float nw0 = fmaf(M00, w0, M10 * w1);
    float nw1 = fmaf(M01, w0, M11 * w1);
    float ne0 = fmaf(A00, nw0, fmaf(A10, nw1, e0));
    float ne1 = fmaf(A01, nw0, fmaf(A11, nw1, e1));
    float V00 = fmaf(M00, lJ00, M10 * lJ01);
    float V01 = fmaf(M00, lJ01, M10 * lJ11);
    float V10 = fmaf(M01, lJ00, M11 * lJ01);
    float V11 = fmaf(M01, lJ01, M11 * lJ11);
    float X00 = fmaf(A00, V00, A10 * V10);
    float X01 = fmaf(A00, V01, A10 * V11);
    float X10 = fmaf(A01, V00, A11 * V10);
    float X11 = fmaf(A01, V01, A11 * V11);
    float nJ00 = fmaf(X00, A00, fmaf(X01, A10, J00));
    float nJ01 = fmaf(X00, A01, fmaf(X01, A11, J01));
    float nJ11 = fmaf(X10, A01, fmaf(X11, A11, J11));
    A00=nA00; A01=nA01; A10=nA10; A11=nA11;
    b0=nb0; b1=nb1; C00=nC00; C01=nC01; C11=nC11;
    e0=ne0; e1=ne1; J00=nJ00; J01=nJ01; J11=nJ11;
}

// ---------------- filter element applied to a state ----------------
__device__ __forceinline__ void fapply(
    float &m0, float &m1, float &p0, float &p1, float &p2,
    float A00, float A01, float A10, float A11,
    float b0, float b1, float C00, float C01, float C11,
    float e0f, float e1f, float J00, float J01, float J11)
{
    float G00 = fmaf(p0, J00, fmaf(p1, J01, 1.0f));
    float G01 = fmaf(p0, J01, p1 * J11);
    float G10 = fmaf(p1, J00, p2 * J01);
    float G11 = fmaf(p1, J01, fmaf(p2, J11, 1.0f));
    float det = fmaf(G00, G11, -(G01 * G10));
    float id  = __fdividef(1.0f, det);
    float M00 =  G11 * id, M01 = -G01 * id, M10 = -G10 * id, M11 = G00 * id;
    float tb0 = fmaf(p0, e0f, fmaf(p1, e1f, m0));
    float tb1 = fmaf(p1, e0f, fmaf(p2, e1f, m1));
    float mt0 = fmaf(M00, tb0, M01 * tb1);
    float mt1 = fmaf(M10, tb0, M11 * tb1);
    float nm0 = fmaf(A00, mt0, fmaf(A01, mt1, b0));
    float nm1 = fmaf(A10, mt0, fmaf(A11, mt1, b1));
    float V00 = fmaf(M00, p0, M01 * p1);
    float V01 = fmaf(M00, p1, M01 * p2);
    float V10 = fmaf(M10, p0, M11 * p1);
    float V11 = fmaf(M10, p1, M11 * p2);
    float X00 = fmaf(A00, V00, A01 * V10);
    float X01 = fmaf(A00, V01, A01 * V11);
    float X10 = fmaf(A10, V00, A11 * V10);
    float X11 = fmaf(A10, V01, A11 * V11);
    float np0 = fmaf(X00, A00, fmaf(X01, A01, C00));
    float np1 = fmaf(X00, A10, fmaf(X01, A11, C01));
    float np2 = fmaf(X10, A10, fmaf(X11, A11, C11));
    m0 = nm0; m1 = nm1; p0 = np0; p1 = np1; p2 = np2;
}

// ---------------- smoother affine apply (compact repr) ----------------
// m' = M m + v ; P' = Wc + s * Gc P Gc^T
__device__ __forceinline__ void sapply(
    float &m0, float &m1, float &p0, float &p1, float &p2,
    float4 sM, float4 sV, float4 sG, float2 sW)
{
    float nm0 = fmaf(sM.x, m0, fmaf(sM.y, m1, sV.x));
    float nm1 = fmaf(sM.z, m0, fmaf(sM.w, m1, sV.y));
    float U0 = fmaf(sG.x, p0, sG.y * p1);
    float U1 = fmaf(sG.x, p1, sG.y * p2);
    float U2 = fmaf(sG.z, p0, sG.w * p1);
    float U3 = fmaf(sG.z, p1, sG.w * p2);
    float np0 = fmaf(sW.y, fmaf(U0, sG.x, U1 * sG.y), sV.z);
    float np1 = fmaf(sW.y, fmaf(U0, sG.z, U1 * sG.w), sV.w);
    float np2 = fmaf(sW.y, fmaf(U2, sG.z, U3 * sG.w), sW.x);
    m0 = nm0; m1 = nm1; p0 = np0; p1 = np1; p2 = np2;
}

// ================= F2: filter chunk composites =================
__global__ void __launch_bounds__(512) fscan_chunk(
    const float* __restrict__ dtn,
    const float* __restrict__ ys,
    const float* __restrict__ rs,
    const float* __restrict__ ls,
    const float* __restrict__ vs)
{
    int c = threadIdx.x;
    int k = blockIdx.x;
    int v = c >> 4, l = c & 15;
    float lam = SQRT3 / ls[l];
    float s2  = vs[l];
    const float* yp = ys + (size_t)v * NT * NL + l;
    const float* rp = rs + (size_t)v * NT * NL + l;
    const float* dp = dtn + (size_t)v * NT1;

    float A00=1.f, A01=0.f, A10=0.f, A11=1.f;
    float b0=0.f, b1=0.f;
    float C00=0.f, C01=0.f, C11=0.f;
    float e0=0.f, e1=0.f;
    float J00=0.f, J01=0.f, J11=0.f;

    int tlo = (k == 0) ? 1 : CHF * k;
    int thi = CHF * k + CHF;
    for (int t = tlo; t < thi; ++t) {
        float dt = dp[t - 1];
        float y  = yp[(size_t)t * NL];
        float r  = rp[(size_t)t * NL];
        float a11,a12,a21,a22,q00,q01,q11;
        make_AQ(dt, lam, s2, a11,a12,a21,a22, q00,q01,q11);
        float S  = q00 + r;
        float iS = __fdividef(1.0f, S);
        float k0 = q00 * iS;
        float k1 = q01 * iS;
        float om = 1.0f - k0;
        float lA00 = om * a11, lA01 = om * a12;
        float lA10 = a21 - k1 * a11, lA11 = a22 - k1 * a12;
        float lb0 = k0 * y, lb1 = k1 * y;
        float lC00 = om * q00, lC01 = om * q01, lC11 = q11 - k1 * q01;
        float ySi = y * iS;
        float le0 = a11 * ySi, le1 = a12 * ySi;
        float lJ00 = a11 * a11 * iS, lJ01 = a11 * a12 * iS, lJ11 = a12 * a12 * iS;
        fcompose(A00,A01,A10,A11,b0,b1,C00,C01,C11,e0,e1,J00,J01,J11,
                 lA00,lA01,lA10,lA11,lb0,lb1,lC00,lC01,lC11,le0,le1,lJ00,lJ01,lJ11);
    }
    int ix = k * NC + c;
    g_feA[ix] = make_float4(A00, A01, A10, A11);
    g_feB[ix] = make_float4(b0, b1, e0, e1);
    g_feC[ix] = make_float4(C00, C01, C11, J00);
    g_feJ[ix] = make_float2(J01, J11);
}

// ================= F2b: compose 16 chunks -> super composites =================
__global__ void __launch_bounds__(512) fcarry1()
{
    int c = threadIdx.x;
    int s = blockIdx.x;
    float A00=1.f, A01=0.f, A10=0.f, A11=1.f;
    float b0=0.f, b1=0.f, C00=0.f, C01=0.f, C11=0.f;
    float e0=0.f, e1=0.f, J00=0.f, J01=0.f, J11=0.f;
    int base = (s * 16) * NC + c;
    #pragma unroll 4
    for (int j = 0; j < 16; ++j) {
        int ix = base + j * NC;
        float4 fA = g_feA[ix], fB = g_feB[ix], fC = g_feC[ix];
        float2 fJ = g_feJ[ix];
        fcompose(A00,A01,A10,A11,b0,b1,C00,C01,C11,e0,e1,J00,J01,J11,
                 fA.x,fA.y,fA.z,fA.w, fB.x,fB.y, fC.x,fC.y,fC.z,
                 fB.z,fB.w, fC.w,fJ.x,fJ.y);
    }
    int ox = s * NC + c;
    g_sfA[ox] = make_float4(A00, A01, A10, A11);
    g_sfB[ox] = make_float4(b0, b1, e0, e1);
    g_sfC[ox] = make_float4(C00, C01, C11, J00);
    g_sfJ[ox] = make_float2(J01, J11);
}

// ================= F3a: serial scan over 16 supers =================
__global__ void __launch_bounds__(512) fcarry2(
    const float* __restrict__ ys,
    const float* __restrict__ rs,
    const float* __restrict__ ls,
    const float* __restrict__ vs)
{
    int c = threadIdx.x;
    int v = c >> 4, l = c & 15;
    float lam = SQRT3 / ls[l];
    float s2  = vs[l];
    float y0 = ys[(size_t)v * NT * NL + l];
    float r0 = rs[(size_t)v * NT * NL + l];
    float s  = s2 + r0;
    float inv = __fdividef(1.0f, s + F_JITTER);
    float w0 = s2 * inv;
    float m0 = w0 * y0, m1 = 0.0f;
    float p0 = s2 - w0 * s2, p1 = 0.0f, p2 = s2 * lam * lam;

    #pragma unroll
    for (int ss = 0; ss < NSF; ++ss) {
        int ix = ss * NC + c;
        g_fbM2[ix] = make_float2(m0, m1);
        g_fbP2[ix] = make_float4(p0, p1, p2, 0.0f);
        float4 fA = g_sfA[ix], fB = g_sfB[ix], fC = g_sfC[ix];
        float2 fJ = g_sfJ[ix];
        fapply(m0,m1,p0,p1,p2,
               fA.x,fA.y,fA.z,fA.w, fB.x,fB.y, fC.x,fC.y,fC.z,
               fB.z,fB.w, fC.w,fJ.x,fJ.y);
    }
    g_ffM[c] = make_float2(m0, m1);
    g_ffP[c] = make_float4(p0, p1, p2, 0.0f);
}

// ================= F4/S2 fused: expand + fused filter/smoother-composite =================
__global__ void __launch_bounds__(512) fsmcomp(
    const float* __restrict__ dtn,
    const float* __restrict__ ys,
    const float* __restrict__ rs,
    const float* __restrict__ ls,
    const float* __restrict__ vs)
{
    int c = threadIdx.x;
    int k = blockIdx.x;
    int v = c >> 4, l = c & 15;
    float lam = SQRT3 / ls[l];
    float s2  = vs[l];
    const float* yp = ys + (size_t)v * NT * NL + l;
    const float* rp = rs + (size_t)v * NT * NL + l;
    const float* dp = dtn + (size_t)v * NT1;

    // smoother composite accumulator (identity): mean (M, v), cov (Gc, Wc, sc)
    float M00=1.f, M01=0.f, M10=0.f, M11=1.f, v0=0.f, v1=0.f;
    float Gc00=1.f, Gc01=0.f, Gc10=0.f, Gc11=1.f;
    float Wc0=0.f, Wc1=0.f, Wc2=0.f;
    float sc = 1.f;

    float m0, m1, p0, p1, p2;
    float a11,a12,a21,a22,q00,q01,q11;
    float mp0,mp1,t00,t01,t10,t11,Pp00,Pp01,Pp11;
    float acc = 0.0f;

#define PREDICT() { \
    mp0 = fmaf(a11, m0, a12 * m1); \
    mp1 = fmaf(a21, m0, a22 * m1); \
    t00 = fmaf(a11, p0, a12 * p1); \
    t01 = fmaf(a11, p1, a12 * p2); \
    t10 = fmaf(a21, p0, a22 * p1); \
    t11 = fmaf(a21, p1, a22 * p2); \
    Pp00 = fmaf(t00, a11, fmaf(t01, a12, q00)); \
    Pp01 = fmaf(t00, a21, fmaf(t01, a22, q01)); \
    Pp11 = fmaf(t10, a21, fmaf(t11, a22, q11)); }

#define UPDATE(yv, rv) { \
    float sv = Pp00 + (rv); \
    float dv = (yv) - mp0; \
    float iv = __fdividef(1.0f, sv + F_JITTER); \
    float wk0 = Pp00 * iv, wk1 = Pp01 * iv; \
    m0 = fmaf(wk0, dv, mp0); \
    m1 = fmaf(wk1, dv, mp1); \
    p0 = fmaf(-wk0, Pp00, Pp00); \
    p1 = fmaf(-wk0, Pp01, Pp01); \
    p2 = fmaf(-wk1, Pp01, Pp11); \
    acc += fmaf(dv * dv, iv, __logf(sv)); }

#define ELEMENT() { \
    float Mj0 = Pp00 + F_JITTER, Mj1 = Pp11 + F_JITTER; \
    float det = fmaf(Mj0, Mj1, -(Pp01 * Pp01)); \
    float di  = __fdividef(1.0f, det); \
    float i00 =  Mj1 * di, i01 = -Pp01 * di, i11 = Mj0 * di; \
    float g00 = fmaf(t00, i00, t10 * i01); \
    float g01 = fmaf(t00, i01, t10 * i11); \
    float g10 = fmaf(t01, i00, t11 * i01); \
    float g11 = fmaf(t01, i01, t11 * i11); \
    float h0 = m0 - fmaf(g00, mp0, g01 * mp1); \
    float h1 = m1 - fmaf(g10, mp0, g11 * mp1); \
    float u00 = fmaf(g00, Pp00, g01 * Pp01); \
    float u01 = fmaf(g00, Pp01, g01 * Pp11); \
    float u10 = fmaf(g10, Pp00, g11 * Pp01); \
    float u11 = fmaf(g10, Pp01, g11 * Pp11); \
    float W0 = p0 + fmaf(u00, g00, u01 * g01); \
    float W1 = p1 + fmaf(u00, g10, u01 * g11); \
    float W2 = p2 + fmaf(u10, g10, u11 * g11); \
    float nM00 = fmaf(M00, g00, M01 * g10); \
    float nM01 = fmaf(M00, g01, M01 * g11); \
    float nM10 = fmaf(M10, g00, M11 * g10); \
    float nM11 = fmaf(M10, g01, M11 * g11); \
    v0 = fmaf(M00, h0, fmaf(M01, h1, v0)); \
    v1 = fmaf(M10, h0, fmaf(M11, h1, v1)); \
    M00=nM00; M01=nM01; M10=nM10; M11=nM11; \
    float U0 = fmaf(Gc00, W0, Gc01 * W1); \
    float U1 = fmaf(Gc00, W1, Gc01 * W2); \
    float U2 = fmaf(Gc10, W0, Gc11 * W1); \
    float U3 = fmaf(Gc10, W1, Gc11 * W2); \
    Wc0 = fmaf(sc, fmaf(U0, Gc00, U1 * Gc01), Wc0); \
    Wc1 = fmaf(sc, fmaf(U0, Gc10, U1 * Gc11), Wc1); \
    Wc2 = fmaf(sc, fmaf(U2, Gc10, U3 * Gc11), Wc2); \
    float nG00 = fmaf(Gc00, g00, Gc01 * g10); \
    float nG01 = fmaf(Gc00, g01, Gc01 * g11); \
    float nG10 = fmaf(Gc10, g00, Gc11 * g10); \
    float nG11 = fmaf(Gc10, g01, Gc11 * g11); \
    Gc00=nG00; Gc01=nG01; Gc10=nG10; Gc11=nG11; \
    sc = -sc; }

#define STORE_SE(qq) { \
    int sx = (qq) * NC + c; \
    g_seM[sx] = make_float4(M00, M01, M10, M11); \
    g_seV[sx] = make_float4(v0, v1, Wc0, Wc1); \
    g_seG[sx] = make_float4(Gc00, Gc01, Gc10, Gc11); \
    g_seW[sx] = make_float2(Wc2, sc); \
    M00=1.f; M01=0.f; M10=0.f; M11=1.f; v0=0.f; v1=0.f; \
    Gc00=1.f; Gc01=0.f; Gc10=0.f; Gc11=1.f; \
    Wc0=0.f; Wc1=0.f; Wc2=0.f; sc=1.f; }

    int e_lo;
    if (k == 0) {
        float y = yp[0], r = rp[0];
        float s = s2 + r;
        float inv = __fdividef(1.0f, s + F_JITTER);
        float wk = s2 * inv;
        m0 = wk * y; m1 = 0.0f;
        p0 = s2 - wk * s2; p1 = 0.0f; p2 = s2 * lam * lam;
        acc = fmaf(y * y, inv, __logf(s));
        e_lo = 0;
    } else {
        // expand chunk boundary from super boundary
        int s = k >> 4;
        float2 bm = g_fbM2[s * NC + c];
        float4 bp = g_fbP2[s * NC + c];
        m0 = bm.x; m1 = bm.y; p0 = bp.x; p1 = bp.y; p2 = bp.z;
        for (int jj = s * 16; jj < k; ++jj) {
            int nx = jj * NC + c;
            float4 fA = g_feA[nx], fB = g_feB[nx], fC = g_feC[nx];
            float2 fJ = g_feJ[nx];
            fapply(m0,m1,p0,p1,p2,
                   fA.x,fA.y,fA.z,fA.w, fB.x,fB.y, fC.x,fC.y,fC.z,
                   fB.z,fB.w, fC.w,fJ.x,fJ.y);
        }
        // publish 16-step boundary q = 2k (filtered at t = 32k - 1)
        g_fbM[(2 * k) * NC + c] = make_float2(m0, m1);
        g_fbP[(2 * k) * NC + c] = make_float4(p0, p1, p2, 0.0f);
        // advance 32k-1 -> 32k (log-lik for step 32k)
        make_AQ(dp[CHF*k - 1], lam, s2, a11,a12,a21,a22, q00,q01,q11);
        PREDICT();
        UPDATE(yp[(size_t)(CHF*k) * NL], rp[(size_t)(CHF*k) * NL]);
        e_lo = CHF * k;
    }
    int e_hi   = (k == NKF - 1) ? (NT - 2) : (CHF * k + CHF - 1);  // last element
    int upd_hi = (k == NKF - 1) ? (NT - 1) : (CHF * k + CHF - 1);  // update while t < upd_hi
    for (int t = e_lo; t <= e_hi; ++t) {
        make_AQ(dp[t], lam, s2, a11,a12,a21,a22, q00,q01,q11);
        PREDICT();
        ELEMENT();   // element t (uses state at t + shared prediction)
        if ((t & 31) == 15) {
            int qb = (t + 1) >> 4;   // odd q: filtered state at t = 16*qb - 1
            g_fbM[qb * NC + c] = make_float2(m0, m1);
            g_fbP[qb * NC + c] = make_float4(p0, p1, p2, 0.0f);
        }
        if ((t & 15) == 15) STORE_SE(t >> 4);
        if (t < upd_hi) {
            UPDATE(yp[(size_t)(t + 1) * NL], rp[(size_t)(t + 1) * NL]);
        }
    }
    if (k == NKF - 1) STORE_SE(NQS - 1);   // elements 8176..8190 (sign = -1 carried)
#undef PREDICT
#undef UPDATE
#undef ELEMENT
#undef STORE_SE
    g_lpp[k * NC + c] = acc;
}

// ================= S2b: compose 32 smoother sub-chunks -> super =================
__global__ void __launch_bounds__(512) scarry1()
{
    int c = threadIdx.x;
    int s = blockIdx.x;
    float M00=1.f, M01=0.f, M10=0.f, M11=1.f, v0=0.f, v1=0.f;
    float Gc00=1.f, Gc01=0.f, Gc10=0.f, Gc11=1.f;
    float Wc0=0.f, Wc1=0.f, Wc2=0.f, sc=1.f;
    int base = s * 32 * NC + c;
    #pragma unroll 4
    for (int j = 31; j >= 0; --j) {
        int ix = base + j * NC;
        float4 eM = g_seM[ix], eV = g_seV[ix], eG = g_seG[ix];
        float2 eW = g_seW[ix];
        // comp <- elem_j o comp (elem applied AFTER comp)
        float nM00 = fmaf(eM.x, M00, eM.y * M10);
        float nM01 = fmaf(eM.x, M01, eM.y * M11);
        float nM10 = fmaf(eM.z, M00, eM.w * M10);
        float nM11 = fmaf(eM.z, M01, eM.w * M11);
        float nv0 = fmaf(eM.x, v0, fmaf(eM.y, v1, eV.x));
        float nv1 = fmaf(eM.z, v0, fmaf(eM.w, v1, eV.y));
        // Wc' = eW + es*(eG Wc eG^T) ; Gc' = eG*Gc ; sc' = es*sc
        float es = eW.y;
        float U0 = fmaf(eG.x, Wc0, eG.y * Wc1);
        float U1 = fmaf(eG.x, Wc1, eG.y * Wc2);
        float U2 = fmaf(eG.z, Wc0, eG.w * Wc1);
        float U3 = fmaf(eG.z, Wc1, eG.w * Wc2);
        float nW0 = fmaf(es, fmaf(U0, eG.x, U1 * eG.y), eV.z);
        float nW1 = fmaf(es, fmaf(U0, eG.z, U1 * eG.w), eV.w);
        float nW2 = fmaf(es, fmaf(U2, eG.z, U3 * eG.w), eW.x);
        float nG00 = fmaf(eG.x, Gc00, eG.y * Gc10);
        float nG01 = fmaf(eG.x, Gc01, eG.y * Gc11);
        float nG10 = fmaf(eG.z, Gc00, eG.w * Gc10);
        float nG11 = fmaf(eG.z, Gc01, eG.w * Gc11);
        M00=nM00; M01=nM01; M10=nM10; M11=nM11; v0=nv0; v1=nv1;
        Gc00=nG00; Gc01=nG01; Gc10=nG10; Gc11=nG11;
        Wc0=nW0; Wc1=nW1; Wc2=nW2;
        sc = es * sc;
    }
    int ox = s * NC + c;
    g_ssM[ox] = make_float4(M00, M01, M10, M11);
    g_ssV[ox] = make_float4(v0, v1, Wc0, Wc1);
    g_ssG[ox] = make_float4(Gc00, Gc01, Gc10, Gc11);
    g_ssW[ox] = make_float2(Wc2, sc);
}

// ================= S3a: serial scan over 16 supers (backward) =================
__global__ void __launch_bounds__(512) scarry2()
{
    int c = threadIdx.x;
    float2 fm = g_ffM[c];
    float4 fp = g_ffP[c];
    float m0 = fm.x, m1 = fm.y;
    float p0 = fp.x, p1 = fp.y, p2 = fp.z;
    #pragma unroll
    for (int s = NSF - 1; s >= 0; --s) {
        int ix = s * NC + c;
        g_sbM2[ix] = make_float2(m0, m1);
        g_sbP2[ix] = make_float4(p0, p1, p2, 0.0f);
        sapply(m0, m1, p0, p1, p2,
               g_ssM[ix], g_ssV[ix], g_ssG[ix], g_ssW[ix]);
    }
}

// ================= SOLVE: 16-step tiles, re-filter + re-smooth + outputs =================
// grid (NQS, 4), block 128, dynamic smem = SOLVE_SMEM
__global__ void __launch_bounds__(128) solve_kernel(
    const float* __restrict__ dtn,
    const float* __restrict__ ys,
    const float* __restrict__ rs,
    const float* __restrict__ ls,
    const float* __restrict__ vs,
    float* __restrict__ out)
{
    extern __shared__ char sh[];
    float2* sm = (float2*)sh;                    // [128][17]
    float4* sp = (float4*)(sh + 128 * 17 * 8);   // [128][17]
#define SM(ch, tl) sm[(ch) * 17 + (tl)]
#define SP(ch, tl) sp[(ch) * 17 + (tl)]

    int tid = threadIdx.x;
    int q = blockIdx.x;
    int cbase = blockIdx.y * 128;
    int c = cbase + tid;
    int v = c >> 4, l = c & 15;
    float lam = SQRT3 / ls[l];
    float s2  = vs[l];
    const float* yp = ys + (size_t)v * NT * NL + l;
    const float* rp = rs + (size_t)v * NT * NL + l;
    const float* dp = dtn + (size_t)v * NT1;
    int t0 = CHS * q;

    // ---- forward: exact filter over sub-chunk, fill smem tile ----
    float m0, m1, p0, p1, p2;
    int tlo;
    if (q == 0) {
        float y = yp[0], r = rp[0];
        float s = s2 + r;
        float inv = __fdividef(1.0f, s + F_JITTER);
        float w0 = s2 * inv;
        m0 = w0 * y; m1 = 0.0f;
        p0 = s2 - w0 * s2; p1 = 0.0f; p2 = s2 * lam * lam;
        SM(tid, 0) = make_float2(m0, m1);
        SP(tid, 0) = make_float4(p0, p1, p1, p2);
        tlo = 1;
    } else {
        float2 bm = g_fbM[q * NC + c];
        float4 bp = g_fbP[q * NC + c];
        m0 = bm.x; m1 = bm.y; p0 = bp.x; p1 = bp.y; p2 = bp.z;
        tlo = t0;
    }
    for (int t = tlo; t < t0 + CHS; ++t) {
        float a11,a12,a21,a22,q00,q01,q11;
        make_AQ(dp[t - 1], lam, s2, a11,a12,a21,a22, q00,q01,q11);
        fstep(m0, m1, p0, p1, p2, a11,a12,a21,a22, q00,q01,q11,
              yp[(size_t)t * NL], rp[(size_t)t * NL]);
        int tl = t - t0;
        SM(tid, tl) = make_float2(m0, m1);
        SP(tid, tl) = make_float4(p0, p1, p1, p2);
    }
    __syncthreads();

    // ---- bulk write filtered m (8 float4 per row) ----
    {
        float4* om4 = (float4*)out;
        int sub = tid & 7, grp = tid >> 3;
        #pragma unroll
        for (int rep = 0; rep < 8; ++rep) {
            int ch = rep * 16 + grp;
            size_t rowb = ((size_t)(cbase + ch) * NT + t0) >> 1;
            float2 a = SM(ch, sub * 2), b = SM(ch, sub * 2 + 1);
            om4[rowb + sub] = make_float4(a.x, a.y, b.x, b.y);
        }
        float4* op = (float4*)(out + OFF_P);
        int sub16 = tid & 15, grp16 = tid >> 4;
        #pragma unroll
        for (int rep = 0; rep < 16; ++rep) {
            int ch = rep * 8 + grp16;
            size_t rowb = (size_t)(cbase + ch) * NT + t0;
            op[rowb + sub16] = SP(ch, sub16);
        }
    }
    __syncthreads();

    // ---- expand smoothed boundary from super boundary, then backward ----
    {
        int s = q >> 5;
        float2 bm = g_sbM2[s * NC + c];
        float4 bp = g_sbP2[s * NC + c];
        float ms0 = bm.x, ms1 = bm.y;
        float s00 = bp.x, s01 = bp.y, s11 = bp.z;
        for (int jj = s * 32 + 31; jj > q; --jj) {
            int ix = jj * NC + c;
            sapply(ms0, ms1, s00, s01, s11,
                   g_seM[ix], g_seV[ix], g_seG[ix], g_seW[ix]);
        }
        int tstart;
        if (q == NQS - 1) {
            SM(tid, CHS - 1) = make_float2(ms0, s00);   // t = NT-1: smoothed == filtered
            tstart = NT - 2;
        } else {
            tstart = t0 + CHS - 1;
        }
        for (int t = tstart; t >= t0; --t) {
            int tl = t - t0;
            float2 mf = SM(tid, tl);
            float4 pf = SP(tid, tl);
            float a11,a12,a21,a22,q00,q01,q11;
            make_AQ(dp[t], lam, s2, a11,a12,a21,a22, q00,q01,q11);
            float g00,g01,g10,g11,h0,h1,W00,W01,W11;
            sgain(mf.x, mf.y, pf.x, pf.y, pf.w, a11,a12,a21,a22, q00,q01,q11,
                  g00,g01,g10,g11, h0,h1, W00,W01,W11);
            float u00 = fmaf(g00, s00, g01 * s01);
            float u01 = fmaf(g00, s01, g01 * s11);
            float u10 = fmaf(g10, s00, g11 * s01);
            float u11 = fmaf(g10, s01, g11 * s11);
            float nm0 = fmaf(g00, ms0, fmaf(g01, ms1, h0));
            float nm1 = fmaf(g10, ms0, fmaf(g11, ms1, h1));
            s00 = W00 - fmaf(u00, g00, u01 * g01);
            s01 = W01 - fmaf(u00, g10, u01 * g11);
            s11 = W11 - fmaf(u10, g10, u11 * g11);
            ms0 = nm0; ms1 = nm1;
            SM(tid, tl) = make_float2(ms0, s00);
        }
    }
    __syncthreads();

    // ---- bulk write mz, pz (4 float4 per row each) ----
    {
        float* omz = out + OFF_MZ;
        float* opz = out + OFF_PZ;
        int sub = tid & 3, grp = tid >> 2;
        #pragma unroll
        for (int rep = 0; rep < 4; ++rep) {
            int ch = rep * 32 + grp;
            size_t rowb = (size_t)(cbase + ch) * NT + t0;
            float2 e0 = SM(ch, sub * 4 + 0);
            float2 e1 = SM(ch, sub * 4 + 1);
            float2 e2 = SM(ch, sub * 4 + 2);
            float2 e3 = SM(ch, sub * 4 + 3);
            ((float4*)(omz + rowb))[sub] = make_float4(e0.x, e1.x, e2.x, e3.x);
            ((float4*)(opz + rowb))[sub] = make_float4(e0.y, e1.y, e2.y, e3.y);
        }
    }
#undef SM
#undef SP
}

// ---------------- deterministic log-lik reduction ----------------
__global__ void __launch_bounds__(512) logp_kernel(float* __restrict__ out)
{
    __shared__ double sh[NC];
    int c = threadIdx.x;
    double a = 0.0;
    #pragma unroll 4
    for (int k = 0; k < NKF; ++k) a += (double)g_lpp[k * NC + c];
    sh[c] = -0.5 * (a + (double)NT * (double)F_LOG2PI);
    __syncthreads();
    if (c < NV) {
        double s = 0.0;
        #pragma unroll
        for (int l = 0; l < NL; ++l) s += sh[c * NL + l];
        out[OFF_LP + c] = (float)s;
    }
}

extern "C" void kernel_launch(void* const* d_in, const int* in_sizes, int n_in,
                              void* d_out, int out_size)
{
    const float* dtn = (const float*)d_in[0];
    const float* ys  = (const float*)d_in[1];
    const float* rs  = (const float*)d_in[2];
    const float* ls  = (const float*)d_in[3];
    const float* vs  = (const float*)d_in[4];
    float* out = (float*)d_out;

    cudaFuncSetAttribute(solve_kernel,
                         cudaFuncAttributeMaxDynamicSharedMemorySize, SOLVE_SMEM);

    fscan_chunk<<<NKF, 512>>>(dtn, ys, rs, ls, vs);
    fcarry1<<<NSF, 512>>>();
    fcarry2<<<1, 512>>>(ys, rs, ls, vs);
    fsmcomp<<<NKF, 512>>>(dtn, ys, rs, ls, vs);
    scarry1<<<NSF, 512>>>();
    scarry2<<<1, 512>>>();
    solve_kernel<<<dim3(NQS, 4), 128, SOLVE_SMEM>>>(dtn, ys, rs, ls, vs, out);
    logp_kernel<<<1, 512>>>(out);
}